// round 5
// baseline (speedup 1.0000x reference)
#include <cuda_runtime.h>
#include <math.h>

// L2loss over bucketized histograms:
//   cum = floor(cumsum(hist)) ; s(p) = count(cum <= p) in [0,256]
//   h(p) = (s == K-1) ? h_prev(p) : min(s, K-1)   (carry across channels)
//   loss = sum_c sqrt( sum_p (h1-h2)^2 )
//
// R5: 112 blocks x 448 threads = 50176 = 1 px/thread, one wave over 112 SMs
// (R4 used only 49 SMs; per-SM issue volume was the binding resource).

namespace {
constexpr int KBINS = 256;
constexpr int NPIX  = 224 * 224;    // 50176
constexpr int TPB   = 448;          // 14 warps
constexpr int NBLK  = NPIX / TPB;   // 112, exact
constexpr int NWARP = TPB / 32;     // 14
}

__device__ unsigned long long g_acc01;   // ch0 in low 32, ch1 in high 32
__device__ unsigned int       g_acc2;    // ch2
__device__ unsigned int       g_ticket;  // self-resetting via atomicInc wrap

__global__ void __launch_bounds__(TPB)
l2hist_kernel(const float* __restrict__ target,
              const float* __restrict__ output,
              float* __restrict__ out)
{
    __shared__ alignas(16) int s_cum[6][KBINS];
    __shared__ unsigned int    s_wred[NWARP][3];

    const int tid  = threadIdx.x;
    const int lane = tid & 31;
    const int warp = tid >> 5;

    // ---- Scan: warp a (a<6) computes floor(cumsum) of array a. ----
    // Lane l owns elements [8l, 8l+8): serial in-lane prefix, Kogge-Stone
    // across lane totals, exclusive offset via shfl_up(1).
    if (warp < 6) {
        const float* src = (warp < 3) ? target + (warp << 8)
                                      : output + ((warp - 3) << 8);
        const float4 v0 = __ldg((const float4*)(src + (lane << 3)));
        const float4 v1 = __ldg((const float4*)(src + (lane << 3) + 4));

        float q0 = v0.x;
        float q1 = q0 + v0.y;
        float q2 = q1 + v0.z;
        float q3 = q2 + v0.w;
        float q4 = q3 + v1.x;
        float q5 = q4 + v1.y;
        float q6 = q5 + v1.z;
        float q7 = q6 + v1.w;          // lane total

        float inc = q7;                // inclusive scan of lane totals
        #pragma unroll
        for (int off = 1; off < 32; off <<= 1) {
            const float n = __shfl_up_sync(0xFFFFFFFFu, inc, off);
            if (lane >= off) inc += n;
        }
        float excl = __shfl_up_sync(0xFFFFFFFFu, inc, 1);
        if (lane == 0) excl = 0.0f;

        int4 w0, w1;
        w0.x = __float2int_rd(excl + q0);
        w0.y = __float2int_rd(excl + q1);
        w0.z = __float2int_rd(excl + q2);
        w0.w = __float2int_rd(excl + q3);
        w1.x = __float2int_rd(excl + q4);
        w1.y = __float2int_rd(excl + q5);
        w1.z = __float2int_rd(excl + q6);
        w1.w = __float2int_rd(excl + q7);
        *(int4*)&s_cum[warp][(lane << 3)]     = w0;
        *(int4*)&s_cum[warp][(lane << 3) + 4] = w1;
    }
    __syncthreads();

    const int p = blockIdx.x * TPB + tid;   // pixel position (< NPIX always)

    // ---- Six interleaved branchless binary searches: count(cum[j] <= p),
    //      saturating at 255; the 256 case disambiguated via cum[255]. ----
    int s[6];
    #pragma unroll
    for (int a = 0; a < 6; ++a) s[a] = 0;
    #pragma unroll
    for (int w = 128; w; w >>= 1) {
        #pragma unroll
        for (int a = 0; a < 6; ++a)
            if (s_cum[a][s[a] + w - 1] <= p) s[a] += w;
    }

    // ---- Carry semantics across channels + squared diffs. ----
    int h1 = 0, h2 = 0;
    unsigned int acc[3];
    #pragma unroll
    for (int c = 0; c < 3; ++c) {
        const int s1 = s[c], s2 = s[c + 3];
        if (s1 != KBINS - 1)                   h1 = s1;
        else if (s_cum[c    ][KBINS - 1] <= p) h1 = KBINS - 1;  // count was 256
        if (s2 != KBINS - 1)                   h2 = s2;
        else if (s_cum[c + 3][KBINS - 1] <= p) h2 = KBINS - 1;  // count was 256
        const int d = h1 - h2;
        acc[c] = (unsigned int)(d * d);
    }

    // ---- Warp reduce then warp0 block-reduce. ----
    #pragma unroll
    for (int c = 0; c < 3; ++c)
        acc[c] = __reduce_add_sync(0xFFFFFFFFu, acc[c]);
    if (lane == 0) {
        s_wred[warp][0] = acc[0];
        s_wred[warp][1] = acc[1];
        s_wred[warp][2] = acc[2];
    }
    __syncthreads();

    if (warp == 0) {
        unsigned int b0 = (lane < NWARP) ? s_wred[lane][0] : 0u;
        unsigned int b1 = (lane < NWARP) ? s_wred[lane][1] : 0u;
        unsigned int b2 = (lane < NWARP) ? s_wred[lane][2] : 0u;
        b0 = __reduce_add_sync(0xFFFFFFFFu, b0);
        b1 = __reduce_add_sync(0xFFFFFFFFu, b1);
        b2 = __reduce_add_sync(0xFFFFFFFFu, b2);
        if (lane == 0) {
            // Channel sums < 2^32 globally, so packed u64 add never carries
            // across the 32-bit lane boundary.
            atomicAdd(&g_acc01, (unsigned long long)b0 |
                                ((unsigned long long)b1 << 32));
            atomicAdd(&g_acc2, b2);
            __threadfence();
            // atomicInc with val=NBLK-1 wraps 111 -> 0: self-resetting ticket.
            const unsigned int prev = atomicInc(&g_ticket, NBLK - 1);
            if (prev == NBLK - 1) {
                __threadfence();
                const unsigned long long a01 = atomicAdd(&g_acc01, 0ULL);
                const unsigned int       a2  = atomicAdd(&g_acc2, 0u);
                const float r0 = sqrtf((float)(unsigned int)(a01 & 0xFFFFFFFFu));
                const float r1 = sqrtf((float)(unsigned int)(a01 >> 32));
                const float r2 = sqrtf((float)a2);
                *out = r0 + r1 + r2;
                g_acc01 = 0ULL; g_acc2 = 0u;   // replay reset
                __threadfence();
            }
        }
    }
}

extern "C" void kernel_launch(void* const* d_in, const int* in_sizes, int n_in,
                              void* d_out, int out_size)
{
    const float* target = (const float*)d_in[0];  // (3, 256, 1) fp32
    const float* output = (const float*)d_in[1];  // (3, 256, 1) fp32
    float* out = (float*)d_out;                   // scalar fp32
    (void)in_sizes; (void)n_in; (void)out_size;

    l2hist_kernel<<<NBLK, TPB>>>(target, output, out);
}

// round 6
// speedup vs baseline: 1.3140x; 1.3140x over previous
#include <cuda_runtime.h>
#include <math.h>
#include <limits.h>

// L2loss over bucketized histograms — ANALYTIC segment version.
// h(p) per channel is a step function whose breakpoints are the cum values.
// Sum_p (h1-h2)^2 = sum over segments [x, next(x)) of len * d^2, where the
// candidate breakpoints are the 6*256 cum values (+ sentinel 0), deduped so
// each distinct value is counted once (first occurrence in array order).
// 1537 segment-threads replace 50176 pixel-threads; the same-address atomic
// ticket tail shrinks from 112 ops to 9.

namespace {
constexpr int KBINS = 256;
constexpr int NPIX  = 224 * 224;          // 50176
constexpr int TPB   = 192;                // 6 warps (one per scan array)
constexpr int NENT  = 6 * KBINS + 1;      // 1537 candidate breakpoints
constexpr int NBLK  = (NENT + TPB - 1) / TPB;  // 9
constexpr int NWARP = TPB / 32;           // 6
}

__device__ unsigned long long g_acc01;   // ch0 low 32, ch1 high 32
__device__ unsigned int       g_acc2;    // ch2
__device__ unsigned int       g_ticket;  // self-resetting via atomicInc wrap

__global__ void __launch_bounds__(TPB)
l2hist_kernel(const float* __restrict__ target,
              const float* __restrict__ output,
              float* __restrict__ out)
{
    __shared__ alignas(16) int s_cum[6][KBINS];
    __shared__ unsigned int    s_wred[NWARP][3];

    const int tid  = threadIdx.x;
    const int lane = tid & 31;
    const int warp = tid >> 5;

    // ---- Scan: warp a computes floor(cumsum) of array a (as in R4/R5). ----
    {
        const float* src = (warp < 3) ? target + (warp << 8)
                                      : output + ((warp - 3) << 8);
        const float4 v0 = __ldg((const float4*)(src + (lane << 3)));
        const float4 v1 = __ldg((const float4*)(src + (lane << 3) + 4));

        float q0 = v0.x;
        float q1 = q0 + v0.y;
        float q2 = q1 + v0.z;
        float q3 = q2 + v0.w;
        float q4 = q3 + v1.x;
        float q5 = q4 + v1.y;
        float q6 = q5 + v1.z;
        float q7 = q6 + v1.w;          // lane total

        float inc = q7;
        #pragma unroll
        for (int off = 1; off < 32; off <<= 1) {
            const float n = __shfl_up_sync(0xFFFFFFFFu, inc, off);
            if (lane >= off) inc += n;
        }
        float excl = __shfl_up_sync(0xFFFFFFFFu, inc, 1);
        if (lane == 0) excl = 0.0f;

        int4 w0, w1;
        w0.x = __float2int_rd(excl + q0);
        w0.y = __float2int_rd(excl + q1);
        w0.z = __float2int_rd(excl + q2);
        w0.w = __float2int_rd(excl + q3);
        w1.x = __float2int_rd(excl + q4);
        w1.y = __float2int_rd(excl + q5);
        w1.z = __float2int_rd(excl + q6);
        w1.w = __float2int_rd(excl + q7);
        *(int4*)&s_cum[warp][(lane << 3)]     = w0;
        *(int4*)&s_cum[warp][(lane << 3) + 4] = w1;
    }
    __syncthreads();

    const int gid = blockIdx.x * TPB + tid;   // candidate-breakpoint id

    unsigned int acc[3] = {0u, 0u, 0u};
    if (gid < NENT) {
        // Breakpoint value x: gid 0 is the sentinel x=0; otherwise entry
        // e = gid-1 maps to array a_src = e>>8, index j_src = e&255.
        int a_src = -1, j_src = 0, x = 0;
        if (gid != 0) {
            const int e = gid - 1;
            a_src = e >> 8;
            j_src = e & (KBINS - 1);
            x = s_cum[a_src][j_src];
        }

        // Saturating searches: s[a] = min(count(cum[a] <= x), 255).
        int s[6];
        #pragma unroll
        for (int a = 0; a < 6; ++a) s[a] = 0;
        #pragma unroll
        for (int w = 128; w; w >>= 1) {
            #pragma unroll
            for (int a = 0; a < 6; ++a)
                if (s_cum[a][s[a] + w - 1] <= x) s[a] += w;
        }

        // Exact counts, presence of x, and next breakpoint > x.
        int  cnt[6];
        bool pres[6];
        int  nxt = NPIX;
        #pragma unroll
        for (int a = 0; a < 6; ++a) {
            int c = s[a];
            if (c == KBINS - 1 && s_cum[a][KBINS - 1] <= x) c = KBINS; // 256
            cnt[a]  = c;
            pres[a] = (c > 0) && (s_cum[a][c - 1] == x);
            const int nv = (c < KBINS) ? s_cum[a][c] : INT_MAX;
            nxt = (nv < nxt) ? nv : nxt;
        }
        const int len = (nxt > x) ? (nxt - x) : 0;   // nxt already <= NPIX

        // Dedup: count this segment only at the first occurrence of x.
        bool canonical;
        if (gid == 0) {
            canonical = !(pres[0] || pres[1] || pres[2] ||
                          pres[3] || pres[4] || pres[5]);
        } else {
            canonical = (j_src == 0) || (s_cum[a_src][j_src - 1] < x);
            #pragma unroll
            for (int a = 0; a < 6; ++a)
                if (a < a_src && pres[a]) canonical = false;
        }

        if (canonical && len > 0) {
            // h values at p = x with cross-channel carry.
            int h1 = 0, h2 = 0;
            #pragma unroll
            for (int c = 0; c < 3; ++c) {
                const int c1 = cnt[c], c2 = cnt[c + 3];
                if (c1 <= KBINS - 2)      h1 = c1;
                else if (c1 == KBINS)     h1 = KBINS - 1;   // count 256
                /* c1 == 255: keep previous channel's value */
                if (c2 <= KBINS - 2)      h2 = c2;
                else if (c2 == KBINS)     h2 = KBINS - 1;
                const int d = h1 - h2;
                // len*d^2 <= 50176*65025 = 3.26e9 < 2^32; channel totals
                // are sums over disjoint segments of total length NPIX,
                // so they also fit in u32.
                acc[c] = (unsigned int)len * (unsigned int)(d * d);
            }
        }
    }

    // ---- Warp reduce then warp0 block-reduce. ----
    #pragma unroll
    for (int c = 0; c < 3; ++c)
        acc[c] = __reduce_add_sync(0xFFFFFFFFu, acc[c]);
    if (lane == 0) {
        s_wred[warp][0] = acc[0];
        s_wred[warp][1] = acc[1];
        s_wred[warp][2] = acc[2];
    }
    __syncthreads();

    if (warp == 0) {
        unsigned int b0 = (lane < NWARP) ? s_wred[lane][0] : 0u;
        unsigned int b1 = (lane < NWARP) ? s_wred[lane][1] : 0u;
        unsigned int b2 = (lane < NWARP) ? s_wred[lane][2] : 0u;
        b0 = __reduce_add_sync(0xFFFFFFFFu, b0);
        b1 = __reduce_add_sync(0xFFFFFFFFu, b1);
        b2 = __reduce_add_sync(0xFFFFFFFFu, b2);
        if (lane == 0) {
            atomicAdd(&g_acc01, (unsigned long long)b0 |
                                ((unsigned long long)b1 << 32));
            atomicAdd(&g_acc2, b2);
            __threadfence();
            // atomicInc with val=NBLK-1 wraps (NBLK-1) -> 0: self-resetting.
            const unsigned int prev = atomicInc(&g_ticket, NBLK - 1);
            if (prev == NBLK - 1) {
                __threadfence();
                const unsigned long long a01 = atomicAdd(&g_acc01, 0ULL);
                const unsigned int       a2  = atomicAdd(&g_acc2, 0u);
                const float r0 = sqrtf((float)(unsigned int)(a01 & 0xFFFFFFFFu));
                const float r1 = sqrtf((float)(unsigned int)(a01 >> 32));
                const float r2 = sqrtf((float)a2);
                *out = r0 + r1 + r2;
                g_acc01 = 0ULL; g_acc2 = 0u;   // replay reset
                __threadfence();
            }
        }
    }
}

extern "C" void kernel_launch(void* const* d_in, const int* in_sizes, int n_in,
                              void* d_out, int out_size)
{
    const float* target = (const float*)d_in[0];  // (3, 256, 1) fp32
    const float* output = (const float*)d_in[1];  // (3, 256, 1) fp32
    float* out = (float*)d_out;                   // scalar fp32
    (void)in_sizes; (void)n_in; (void)out_size;

    l2hist_kernel<<<NBLK, TPB>>>(target, output, out);
}